// round 14
// baseline (speedup 1.0000x reference)
#include <cuda_runtime.h>
#include <cuda_bf16.h>
#include <math.h>

// ---------------------------------------------------------------------------
// MoE router (TOP_K=2, N_EXP=8).
// Output (float32): [0..8) used_capacity | [8..8+R) cb_weight | [8+R..8+2R) sec_mask
//   where R = N*8*C.
//
// Kernel 1 (persistent, 148 CTAs x 1024, one per SM), SM-LEVEL specialization
// (intra-CTA warp specialization throttled stores via the shared MIO pipe in
//  R10-R13; here each SM runs a single instruction mix):
//   CTA 0..7   : router — 32 warps each, 16 tokens/warp, smem w_g.
//   CTA 8      : rank — spin-join router, ordered per-expert scan,
//                used_capacity (+ tail).
//   CTA 9..147 : pure zero-fill, R9's proven grid-stride STG.128 loop
//                (139 SMs at ~6.3 TB/s => ~53us for 336MB).
// Kernel 2: wide-grid scatter of the 2N nonzeros (kernel boundary = fill sync).
// g_done_router: release-fence + atomicAdd per router warp; the single waiter
// (CTA 8) subtracts the target after observing it => replays start from zero.
// ---------------------------------------------------------------------------

#define N_EXP 8
#define MAXN 65536
#define GRID 148
#define BLOCK 1024
#define ROUTER_CTAS 8
#define RANK_CTA 8
#define FILL_CTAS (GRID - ROUTER_CTAS - 1)            // 139
#define R_WARPS (ROUTER_CTAS * 32)                    // 256 router warps
#define F_THREADS ((long long)FILL_CTAS * BLOCK)      // 142336 fill threads

__device__ int          g_eidx[2 * MAXN];
__device__ float        g_pval[2 * MAXN];
__device__ int          g_rank[2 * MAXN];
__device__ unsigned int g_done_router;   // zero-init; self-resetting

__global__ void __launch_bounds__(BLOCK, 1) fused_kernel(
    const float* __restrict__ x, const float* __restrict__ w_g,
    float* __restrict__ out, int N, int C, long long out_elems)
{
    __shared__ float4 ws[N_EXP * 256];          // 32KB w_g (router CTAs)
    __shared__ int warpcnt[N_EXP][32];          // rank CTA
    __shared__ int basesh[N_EXP][32];
    __shared__ int running[N_EXP];

    const int tid  = threadIdx.x;
    const int warp = tid >> 5;
    const int lane = tid & 31;
    const int b    = blockIdx.x;

    const long long fillF4 = (out_elems - 8) >> 2;       // float4 count
    float4* const   fill4  = reinterpret_cast<float4*>(out + 8);

    if (b > RANK_CTA) {
        // ================= FILL CTAs: pure store stream =================
        const long long ftid = (long long)(b - RANK_CTA - 1) * BLOCK + tid;
        const float4 z = make_float4(0.f, 0.f, 0.f, 0.f);
        for (long long i = ftid; i < fillF4; i += F_THREADS)
            fill4[i] = z;
        return;
    }

    if (b < ROUTER_CTAS) {
        // ================= ROUTER CTAs: 32 warps, 16 tokens/warp ==========
        const float4* wg4 = reinterpret_cast<const float4*>(w_g);
#pragma unroll
        for (int r = 0; r < 2; r++)
            ws[r * BLOCK + tid] = wg4[r * BLOCK + tid];
        __syncthreads();

        const int rw = b * 32 + warp;                    // 0..255

        for (int token = rw; token < N; token += R_WARPS) {
            const float4* x4 =
                reinterpret_cast<const float4*>(x) + (size_t)token * 256;

            float acc[N_EXP];
#pragma unroll
            for (int e = 0; e < N_EXP; e++) acc[e] = 0.0f;

#pragma unroll
            for (int j = 0; j < 8; j++) {
                float4 xv = x4[j * 32 + lane];
#pragma unroll
                for (int e = 0; e < N_EXP; e++) {
                    float4 wv = ws[e * 256 + j * 32 + lane];
                    acc[e] += xv.x * wv.x + xv.y * wv.y +
                              xv.z * wv.z + xv.w * wv.w;
                }
            }

#pragma unroll
            for (int off = 16; off > 0; off >>= 1)
#pragma unroll
                for (int e = 0; e < N_EXP; e++)
                    acc[e] += __shfl_down_sync(0xFFFFFFFFu, acc[e], off);

            if (lane == 0) {
                int e0 = 0; float b0 = acc[0];
#pragma unroll
                for (int e = 1; e < N_EXP; e++)
                    if (acc[e] > b0) { b0 = acc[e]; e0 = e; }
                int e1 = (e0 == 0) ? 1 : 0; float b1 = acc[e1];
#pragma unroll
                for (int e = 0; e < N_EXP; e++)
                    if (e != e0 && acc[e] > b1) { b1 = acc[e]; e1 = e; }

                float sum = 0.0f;
#pragma unroll
                for (int e = 0; e < N_EXP; e++) sum += expf(acc[e] - b0);
                float inv = 1.0f / sum;

                g_eidx[token]     = e0;
                g_eidx[N + token] = e1;
                g_pval[token]     = inv;
                g_pval[N + token] = expf(b1 - b0) * inv;
            }
        }
        __syncwarp();
        if (lane == 0) {
            __threadfence();
            atomicAdd(&g_done_router, 1u);
        }
        return;
    }

    // ============== RANK CTA (b == 8): spin-join, scan, epilogue ==========
    if (tid < N_EXP) running[tid] = 0;

    if (tid == 0) {
        while (atomicAdd(&g_done_router, 0u) < (unsigned)R_WARPS) { }
        atomicSub(&g_done_router, (unsigned)R_WARPS);    // reset for replay
        __threadfence();
    }
    __syncthreads();

    const int total = 2 * N;
    const int rounds = (total + BLOCK - 1) / BLOCK;
    for (int rd = 0; rd < rounds; rd++) {
        const int i = rd * BLOCK + tid;
        const int e = (i < total) ? g_eidx[i] : -1;

        if (tid < N_EXP * 32) ((int*)warpcnt)[tid] = 0;
        __syncthreads();

        unsigned m = __match_any_sync(0xFFFFFFFFu, e);
        int lrank  = __popc(m & ((1u << lane) - 1u));
        int leader = __ffs(m) - 1;
        if (e >= 0 && lane == leader)
            warpcnt[e][warp] = __popc(m);
        __syncthreads();

        if (warp < N_EXP) {
            int runv = running[warp];
            int v = warpcnt[warp][lane];
            int s = v;
#pragma unroll
            for (int off = 1; off < 32; off <<= 1) {
                int u = __shfl_up_sync(0xFFFFFFFFu, s, off);
                if (lane >= off) s += u;
            }
            basesh[warp][lane] = runv + s - v;
            if (lane == 31) running[warp] = runv + s;
        }
        __syncthreads();

        if (e >= 0)
            g_rank[i] = basesh[e][warp] + lrank;
        __syncthreads();
    }

    // used_capacity (out[0..8) is outside the fill region)
    if (tid < N_EXP) {
        int uc = running[tid];
        if (uc > C) uc = C;
        out[tid] = (float)uc;
    }

    // tail floats not covered by float4 fill (none when C even, but safe)
    {
        long long done = 8 + (((out_elems - 8) >> 2) << 2);
        for (long long i = done + tid; i < out_elems; i += BLOCK)
            out[i] = 0.0f;
    }
}

// ---------------------------------------------------------------------------
// Kernel 2: wide-grid scatter. One thread per routed entry: at most 2 stores
// into the (already-zeroed) output.
// ---------------------------------------------------------------------------
__global__ void __launch_bounds__(256) scatter_kernel(
    float* __restrict__ out, int N, int C)
{
    const int i = blockIdx.x * blockDim.x + threadIdx.x;
    const int total = 2 * N;
    const long long rowsC = (long long)N * N_EXP * (long long)C;

    if (i < total) {
        int r = g_rank[i];
        if (r < C) {
            int e = g_eidx[i];
            int k = (i >= N) ? 1 : 0;
            int n = i - k * N;
            long long pos = ((long long)n * N_EXP + e) * (long long)C + r;
            out[8 + pos]         = g_pval[i];
            out[8 + rowsC + pos] = 1.0f;
        }
    }
}

// ---------------------------------------------------------------------------
extern "C" void kernel_launch(void* const* d_in, const int* in_sizes, int n_in,
                              void* d_out, int out_size)
{
    const float* x   = (const float*)d_in[0];
    const float* w_g = (const float*)d_in[1];
    float* out = (float*)d_out;

    const int D = in_sizes[1] / N_EXP;   // 1024
    const int N = in_sizes[0] / D;       // 4096 tokens

    int C = (int)floorf(2.0f * 1.25f * (float)N / (float)N_EXP);
    C += (C & 1);
    if (C < 4) C = 4;

    // 1) fused: SM-specialized fill (139 SMs) || router (8 SMs) -> rank (1 SM)
    fused_kernel<<<GRID, BLOCK>>>(x, w_g, out, N, C, (long long)out_size);

    // 2) wide-grid scatter of the 2N nonzeros
    int sblocks = (2 * N + 255) / 256;
    scatter_kernel<<<sblocks, 256>>>(out, N, C);
}

// round 15
// speedup vs baseline: 2.6847x; 2.6847x over previous
#include <cuda_runtime.h>
#include <cuda_bf16.h>
#include <math.h>

// ---------------------------------------------------------------------------
// MoE router (TOP_K=2, N_EXP=8). Output layout (float32, flattened tuple):
//   [0..8)                      used_capacity
//   [8 .. 8+N*8*C)              cb_weight[N,8,C]
//   [8+N*8*C .. 8+2*N*8*C)      sec_mask[N,8,C] (0.0/1.0)
//
// Pipeline (3 graph nodes, serial):
//   1. cudaMemsetAsync (336MB zero fill, HBM-write floor ~52us)
//   2. router kernel (512 CTAs x 256, 1 token/warp, smem w_g — measured 11.6us)
//      + LAST-BLOCK rank scan fused in (saves a launch + cold start)
//   3. wide-grid scatter of the 2N nonzeros + used_capacity
// ---------------------------------------------------------------------------

#define N_EXP 8
#define MAXN 65536

__device__ int          g_eidx[2 * MAXN];   // [k*N+n] -> expert of k-th choice
__device__ float        g_pval[2 * MAXN];   // [k*N+n] -> softmax prob
__device__ int          g_rank[2 * MAXN];   // [k*N+n] -> rank in expert queue
__device__ int          g_total[N_EXP];     // per-expert counts (pre-clamp)
__device__ unsigned int g_done_ctr;         // zero-init; last block resets

// ---------------------------------------------------------------------------
// Router: logits = x @ w_g^T, top-2 (lowest-index tie break), softmax probs.
// 1 token per warp, 8 warps/block, w_g staged in shared (R2 config, 11.6us).
// The last block to finish performs the ordered per-expert rank scan.
// ---------------------------------------------------------------------------
__global__ void __launch_bounds__(256) router_rank_kernel(
    const float* __restrict__ x, const float* __restrict__ w_g, int N, int C)
{
    __shared__ float4 ws[N_EXP * 256];  // 8 x 1024 floats (D=1024)
    __shared__ int warpcnt[N_EXP][8];
    __shared__ int basesh[N_EXP][8];
    __shared__ int running[N_EXP];
    __shared__ bool is_last;

    const int tid  = threadIdx.x;
    const int warp = tid >> 5;
    const int lane = tid & 31;

    const float4* wg4 = reinterpret_cast<const float4*>(w_g);
#pragma unroll
    for (int r = 0; r < 8; r++)
        ws[r * 256 + tid] = wg4[r * 256 + tid];
    __syncthreads();

    const int token = blockIdx.x * 8 + warp;
    if (token < N) {
        const float4* x4 =
            reinterpret_cast<const float4*>(x) + (size_t)token * 256;

        float acc[N_EXP];
#pragma unroll
        for (int e = 0; e < N_EXP; e++) acc[e] = 0.0f;

#pragma unroll
        for (int j = 0; j < 8; j++) {
            float4 xv = x4[j * 32 + lane];
#pragma unroll
            for (int e = 0; e < N_EXP; e++) {
                float4 wv = ws[e * 256 + j * 32 + lane];
                acc[e] += xv.x * wv.x + xv.y * wv.y +
                          xv.z * wv.z + xv.w * wv.w;
            }
        }

#pragma unroll
        for (int off = 16; off > 0; off >>= 1)
#pragma unroll
            for (int e = 0; e < N_EXP; e++)
                acc[e] += __shfl_down_sync(0xFFFFFFFFu, acc[e], off);

        if (lane == 0) {
            int e0 = 0; float b0 = acc[0];
#pragma unroll
            for (int e = 1; e < N_EXP; e++)
                if (acc[e] > b0) { b0 = acc[e]; e0 = e; }
            int e1 = (e0 == 0) ? 1 : 0; float b1 = acc[e1];
#pragma unroll
            for (int e = 0; e < N_EXP; e++)
                if (e != e0 && acc[e] > b1) { b1 = acc[e]; e1 = e; }

            float sum = 0.0f;
#pragma unroll
            for (int e = 0; e < N_EXP; e++) sum += expf(acc[e] - b0);
            float inv = 1.0f / sum;

            g_eidx[token]     = e0;
            g_eidx[N + token] = e1;
            g_pval[token]     = inv;              // expf(0)*inv
            g_pval[N + token] = expf(b1 - b0) * inv;
        }
    }

    // ---- last-block election ----
    __syncthreads();
    if (tid == 0) {
        __threadfence();   // publish this CTA's g_eidx/g_pval
        unsigned prev = atomicAdd(&g_done_ctr, 1u);
        is_last = (prev == gridDim.x - 1);
        if (is_last) {
            atomicExch(&g_done_ctr, 0u);   // reset for next replay
            __threadfence();               // acquire all CTAs' writes
        }
    }
    __syncthreads();
    if (!is_last) return;

    // =============== LAST BLOCK: ordered per-expert rank scan ===============
    if (tid < N_EXP) running[tid] = 0;

    const int total = 2 * N;
    const int rounds = (total + 255) >> 8;
    for (int rd = 0; rd < rounds; rd++) {
        const int i = rd * 256 + tid;
        const int e = (i < total) ? g_eidx[i] : -1;

        if (tid < N_EXP * 8) ((int*)warpcnt)[tid] = 0;
        __syncthreads();

        unsigned m = __match_any_sync(0xFFFFFFFFu, e);
        int lrank  = __popc(m & ((1u << lane) - 1u));
        int leader = __ffs(m) - 1;
        if (e >= 0 && lane == leader)
            warpcnt[e][warp] = __popc(m);
        __syncthreads();

        if (warp == 0 && lane < N_EXP * 8) {
            // lane = ex*8 + w : scan 8 warp counts per expert serially-cheap
            // do it with a simple per-expert prefix by 8 lanes
        }
        // per-expert scan over 8 warp counts: warps 0..7 handle expert=warp
        if (warp < N_EXP) {
            int runv = running[warp];
            int v = (lane < 8) ? warpcnt[warp][lane] : 0;
            int s = v;
#pragma unroll
            for (int off = 1; off < 8; off <<= 1) {
                int u = __shfl_up_sync(0xFFFFFFFFu, s, off);
                if (lane >= off) s += u;
            }
            if (lane < 8) basesh[warp][lane] = runv + s - v;
            if (lane == 7) running[warp] = runv + s;
        }
        __syncthreads();

        if (e >= 0)
            g_rank[i] = basesh[e][warp] + lrank;
        __syncthreads();
    }

    if (tid < N_EXP)
        g_total[tid] = running[tid];
}

// ---------------------------------------------------------------------------
// Scatter: one thread per routed entry, at most 2 stores into the zeroed
// output. Block 0 writes used_capacity.
// ---------------------------------------------------------------------------
__global__ void __launch_bounds__(256) scatter_kernel(
    float* __restrict__ out, int N, int C)
{
    const int i = blockIdx.x * blockDim.x + threadIdx.x;
    const int total = 2 * N;
    const long long rowsC = (long long)N * N_EXP * (long long)C;

    if (i < total) {
        int r = g_rank[i];
        if (r < C) {
            int e = g_eidx[i];
            int k = (i >= N) ? 1 : 0;
            int n = i - k * N;
            long long pos = ((long long)n * N_EXP + e) * (long long)C + r;
            out[8 + pos]         = g_pval[i];
            out[8 + rowsC + pos] = 1.0f;
        }
    }

    if (blockIdx.x == 0 && threadIdx.x < N_EXP) {
        int uc = g_total[threadIdx.x];
        if (uc > C) uc = C;
        out[threadIdx.x] = (float)uc;
    }
}

// ---------------------------------------------------------------------------
extern "C" void kernel_launch(void* const* d_in, const int* in_sizes, int n_in,
                              void* d_out, int out_size)
{
    const float* x   = (const float*)d_in[0];
    const float* w_g = (const float*)d_in[1];
    float* out = (float*)d_out;

    const int D = in_sizes[1] / N_EXP;   // 1024
    const int N = in_sizes[0] / D;       // 4096 tokens

    int C = (int)floorf(2.0f * 1.25f * (float)N / (float)N_EXP);
    C += (C & 1);
    if (C < 4) C = 4;

    // 1) zero the full output (HBM-write floor ~52us for 336MB)
    cudaMemsetAsync(d_out, 0, (size_t)out_size * sizeof(float));

    // 2) router (R2 config: 1 token/warp, 512 blocks) + last-block rank scan
    int blocks = (N + 7) / 8;
    router_rank_kernel<<<blocks, 256>>>(x, w_g, N, C);

    // 3) wide-grid scatter + used_capacity
    int sblocks = (2 * N + 255) / 256;
    scatter_kernel<<<sblocks, 256>>>(out, N, C);
}

// round 16
// speedup vs baseline: 2.9920x; 1.1145x over previous
#include <cuda_runtime.h>
#include <cuda_bf16.h>
#include <math.h>

// ---------------------------------------------------------------------------
// MoE router (TOP_K=2, N_EXP=8). Output layout (float32, flattened tuple):
//   [0..8)                      used_capacity
//   [8 .. 8+N*8*C)              cb_weight[N,8,C]
//   [8+N*8*C .. 8+2*N*8*C)      sec_mask[N,8,C] (0.0/1.0)
//
// Pipeline (serial, the only structure that has ever measured fastest):
//   1. cudaMemsetAsync            (336MB zero fill, ~52us HBM-write floor)
//   2. router kernel (split-D: 2 warps/token, 1024 CTAs — halves the
//      per-warp latency chain and doubles warp parallelism vs R2's 11.6us)
//   3. rank kernel (1024 threads, 1 block, pure compute — measured ~2.5us)
//   4. wide-grid scatter + used_capacity
// ---------------------------------------------------------------------------

#define N_EXP 8
#define MAXN 65536

__device__ int   g_eidx[2 * MAXN];   // [k*N+n] -> expert of k-th choice
__device__ float g_pval[2 * MAXN];   // [k*N+n] -> softmax prob
__device__ int   g_rank[2 * MAXN];   // [k*N+n] -> rank within expert queue
__device__ int   g_total[N_EXP];     // per-expert routed counts (pre-clamp)

// ---------------------------------------------------------------------------
// Router: logits = x @ w_g^T, top-2 (lowest-index tie break), softmax.
// Split-D: warps (2t, 2t+1) each compute 512 of token t's 1024 elements
// (4 j-steps instead of 8), combine via smem. 4 tokens/block, 1024 blocks.
// ---------------------------------------------------------------------------
__global__ void __launch_bounds__(256) router_topk_kernel(
    const float* __restrict__ x, const float* __restrict__ w_g, int N)
{
    __shared__ float4 ws[N_EXP * 256];       // 8 x 1024 floats (D=1024)
    __shared__ float  part[4][2][N_EXP];     // per-token half-sums

    const int tid  = threadIdx.x;
    const int warp = tid >> 5;
    const int lane = tid & 31;

    // stage w_g (32KB) — identical to the measured-best R2 prologue
    const float4* wg4 = reinterpret_cast<const float4*>(w_g);
#pragma unroll
    for (int r = 0; r < 8; r++)
        ws[r * 256 + tid] = wg4[r * 256 + tid];
    __syncthreads();

    const int tloc  = warp >> 1;            // 0..3 token within block
    const int half  = warp & 1;             // which 512-element half
    const int token = blockIdx.x * 4 + tloc;

    if (token < N) {
        const float4* x4 =
            reinterpret_cast<const float4*>(x) + (size_t)token * 256;

        float acc[N_EXP];
#pragma unroll
        for (int e = 0; e < N_EXP; e++) acc[e] = 0.0f;

#pragma unroll
        for (int jj = 0; jj < 4; jj++) {
            const int j = half * 4 + jj;
            float4 xv = x4[j * 32 + lane];
#pragma unroll
            for (int e = 0; e < N_EXP; e++) {
                float4 wv = ws[e * 256 + j * 32 + lane];
                acc[e] += xv.x * wv.x + xv.y * wv.y +
                          xv.z * wv.z + xv.w * wv.w;
            }
        }

#pragma unroll
        for (int off = 16; off > 0; off >>= 1)
#pragma unroll
            for (int e = 0; e < N_EXP; e++)
                acc[e] += __shfl_down_sync(0xFFFFFFFFu, acc[e], off);

        if (lane == 0) {
#pragma unroll
            for (int e = 0; e < N_EXP; e++)
                part[tloc][half][e] = acc[e];
        }
    }
    __syncthreads();

    // one lane per token finalizes: combine halves, top-2, softmax
    if (warp < 4 && lane == 0) {
        const int t = warp;
        const int tok = blockIdx.x * 4 + t;
        if (tok < N) {
            float a[N_EXP];
#pragma unroll
            for (int e = 0; e < N_EXP; e++)
                a[e] = part[t][0][e] + part[t][1][e];

            int e0 = 0; float b0 = a[0];
#pragma unroll
            for (int e = 1; e < N_EXP; e++)
                if (a[e] > b0) { b0 = a[e]; e0 = e; }
            int e1 = (e0 == 0) ? 1 : 0; float b1 = a[e1];
#pragma unroll
            for (int e = 0; e < N_EXP; e++)
                if (e != e0 && a[e] > b1) { b1 = a[e]; e1 = e; }

            float sum = 0.0f;
#pragma unroll
            for (int e = 0; e < N_EXP; e++) sum += expf(a[e] - b0);
            float inv = 1.0f / sum;

            g_eidx[tok]     = e0;
            g_eidx[N + tok] = e1;
            g_pval[tok]     = inv;               // expf(0)*inv
            g_pval[N + tok] = expf(b1 - b0) * inv;
        }
    }
}

// ---------------------------------------------------------------------------
// Rank: ordered per-expert cumsum (k-major, token order) via match_any+popc
// within warp, per-expert cross-warp scan by warps 0..7. Pure compute.
// ---------------------------------------------------------------------------
__global__ void __launch_bounds__(1024) rank_kernel(int N)
{
    const int tid  = threadIdx.x;
    const int warp = tid >> 5;
    const int lane = tid & 31;
    const int total = 2 * N;

    __shared__ int warpcnt[N_EXP][32];
    __shared__ int basesh[N_EXP][32];
    __shared__ int running[N_EXP];
    if (tid < N_EXP) running[tid] = 0;

    const int rounds = (total + 1023) >> 10;
    for (int rd = 0; rd < rounds; rd++) {
        const int i = rd * 1024 + tid;
        const int e = (i < total) ? g_eidx[i] : -1;

        if (tid < N_EXP * 32) ((int*)warpcnt)[tid] = 0;
        __syncthreads();

        unsigned m = __match_any_sync(0xFFFFFFFFu, e);
        int lrank  = __popc(m & ((1u << lane) - 1u));
        int leader = __ffs(m) - 1;
        if (e >= 0 && lane == leader)
            warpcnt[e][warp] = __popc(m);
        __syncthreads();

        if (warp < N_EXP) {
            int runv = running[warp];
            int v = warpcnt[warp][lane];
            int s = v;
#pragma unroll
            for (int off = 1; off < 32; off <<= 1) {
                int u = __shfl_up_sync(0xFFFFFFFFu, s, off);
                if (lane >= off) s += u;
            }
            basesh[warp][lane] = runv + s - v;   // exclusive + running
            if (lane == 31) running[warp] = runv + s;
        }
        __syncthreads();

        if (e >= 0)
            g_rank[i] = basesh[e][warp] + lrank;
        __syncthreads();
    }

    if (tid < N_EXP)
        g_total[tid] = running[tid];
}

// ---------------------------------------------------------------------------
// Scatter: one thread per routed entry, at most 2 stores into the zeroed
// output. Block 0 writes used_capacity.
// ---------------------------------------------------------------------------
__global__ void __launch_bounds__(256) scatter_kernel(
    float* __restrict__ out, int N, int C)
{
    const int i = blockIdx.x * blockDim.x + threadIdx.x;
    const int total = 2 * N;
    const long long rowsC = (long long)N * N_EXP * (long long)C;

    if (i < total) {
        int r = g_rank[i];
        if (r < C) {
            int e = g_eidx[i];
            int k = (i >= N) ? 1 : 0;
            int n = i - k * N;
            long long pos = ((long long)n * N_EXP + e) * (long long)C + r;
            out[8 + pos]         = g_pval[i];
            out[8 + rowsC + pos] = 1.0f;
        }
    }

    if (blockIdx.x == 0 && threadIdx.x < N_EXP) {
        int uc = g_total[threadIdx.x];
        if (uc > C) uc = C;
        out[threadIdx.x] = (float)uc;
    }
}

// ---------------------------------------------------------------------------
extern "C" void kernel_launch(void* const* d_in, const int* in_sizes, int n_in,
                              void* d_out, int out_size)
{
    const float* x   = (const float*)d_in[0];
    const float* w_g = (const float*)d_in[1];
    float* out = (float*)d_out;

    const int D = in_sizes[1] / N_EXP;   // 1024
    const int N = in_sizes[0] / D;       // 4096 tokens

    int C = (int)floorf(2.0f * 1.25f * (float)N / (float)N_EXP);
    C += (C & 1);
    if (C < 4) C = 4;

    // 1) zero the full output (HBM-write floor for 336MB)
    cudaMemsetAsync(d_out, 0, (size_t)out_size * sizeof(float));

    // 2) router: split-D, 2 warps/token, 4 tokens/block, 1024 blocks
    int blocks = (N + 3) / 4;
    router_topk_kernel<<<blocks, 256>>>(x, w_g, N);

    // 3) ordered ranks (pure compute, single 1024-thread block)
    rank_kernel<<<1, 1024>>>(N);

    // 4) wide-grid scatter + used_capacity
    int sblocks = (2 * N + 255) / 256;
    scatter_kernel<<<sblocks, 256>>>(out, N, C);
}

// round 17
// speedup vs baseline: 3.0053x; 1.0045x over previous
#include <cuda_runtime.h>
#include <cuda_bf16.h>
#include <math.h>

// ---------------------------------------------------------------------------
// MoE router (TOP_K=2, N_EXP=8). Output layout (float32, flattened tuple):
//   [0..8)                      used_capacity
//   [8 .. 8+N*8*C)              cb_weight[N,8,C]
//   [8+N*8*C .. 8+2*N*8*C)      sec_mask[N,8,C] (0.0/1.0)
//
// Pipeline (serial — measured-best structure):
//   1. cudaMemsetAsync (336MB zero fill, ~52us HBM-write floor)
//   2. router (split-D: 2 warps/token, 1024 CTAs) with x PREFETCHED into
//      4 registers BEFORE w_g staging: MLP=4 on the x stream instead of 1,
//      and the DRAM latency overlaps staging + __syncthreads.
//   3. rank kernel (1 block x 1024, pure compute, ~2.5us)
//   4. wide-grid scatter + used_capacity
// ---------------------------------------------------------------------------

#define N_EXP 8
#define MAXN 65536

__device__ int   g_eidx[2 * MAXN];   // [k*N+n] -> expert of k-th choice
__device__ float g_pval[2 * MAXN];   // [k*N+n] -> softmax prob
__device__ int   g_rank[2 * MAXN];   // [k*N+n] -> rank within expert queue
__device__ int   g_total[N_EXP];     // per-expert routed counts (pre-clamp)

// ---------------------------------------------------------------------------
// Router: logits = x @ w_g^T, top-2 (lowest-index tie break), softmax.
// Split-D: warps (2t, 2t+1) each compute 512 of token t's 1024 dims.
// ---------------------------------------------------------------------------
__global__ void __launch_bounds__(256) router_topk_kernel(
    const float* __restrict__ x, const float* __restrict__ w_g, int N)
{
    __shared__ float4 ws[N_EXP * 256];       // 8 x 1024 floats (D=1024)
    __shared__ float  part[4][2][N_EXP];     // per-token half-sums

    const int tid  = threadIdx.x;
    const int warp = tid >> 5;
    const int lane = tid & 31;

    const int tloc  = warp >> 1;            // 0..3 token within block
    const int half  = warp & 1;             // which 512-element half
    const int token = blockIdx.x * 4 + tloc;
    const bool act  = token < N;

    // ---- prefetch this warp's 4 x-chunks FIRST: 4 LDG.128 in flight,
    //      latency overlapped with the staging loop + barrier below ----
    float4 xv[4];
    if (act) {
        const float4* x4 =
            reinterpret_cast<const float4*>(x) + (size_t)token * 256;
#pragma unroll
        for (int jj = 0; jj < 4; jj++)
            xv[jj] = x4[(half * 4 + jj) * 32 + lane];
    }

    // ---- stage w_g (32KB) while x loads are in flight ----
    const float4* wg4 = reinterpret_cast<const float4*>(w_g);
#pragma unroll
    for (int r = 0; r < 8; r++)
        ws[r * 256 + tid] = wg4[r * 256 + tid];
    __syncthreads();

    if (act) {
        float acc[N_EXP];
#pragma unroll
        for (int e = 0; e < N_EXP; e++) acc[e] = 0.0f;

#pragma unroll
        for (int jj = 0; jj < 4; jj++) {
            const int j = half * 4 + jj;
#pragma unroll
            for (int e = 0; e < N_EXP; e++) {
                float4 wv = ws[e * 256 + j * 32 + lane];
                acc[e] += xv[jj].x * wv.x + xv[jj].y * wv.y +
                          xv[jj].z * wv.z + xv[jj].w * wv.w;
            }
        }

#pragma unroll
        for (int off = 16; off > 0; off >>= 1)
#pragma unroll
            for (int e = 0; e < N_EXP; e++)
                acc[e] += __shfl_down_sync(0xFFFFFFFFu, acc[e], off);

        if (lane == 0) {
#pragma unroll
            for (int e = 0; e < N_EXP; e++)
                part[tloc][half][e] = acc[e];
        }
    }
    __syncthreads();

    // one lane per token finalizes: combine halves, top-2, softmax
    if (warp < 4 && lane == 0) {
        const int t = warp;
        const int tok = blockIdx.x * 4 + t;
        if (tok < N) {
            float a[N_EXP];
#pragma unroll
            for (int e = 0; e < N_EXP; e++)
                a[e] = part[t][0][e] + part[t][1][e];

            int e0 = 0; float b0 = a[0];
#pragma unroll
            for (int e = 1; e < N_EXP; e++)
                if (a[e] > b0) { b0 = a[e]; e0 = e; }
            int e1 = (e0 == 0) ? 1 : 0; float b1 = a[e1];
#pragma unroll
            for (int e = 0; e < N_EXP; e++)
                if (e != e0 && a[e] > b1) { b1 = a[e]; e1 = e; }

            float sum = 0.0f;
#pragma unroll
            for (int e = 0; e < N_EXP; e++) sum += expf(a[e] - b0);
            float inv = 1.0f / sum;

            g_eidx[tok]     = e0;
            g_eidx[N + tok] = e1;
            g_pval[tok]     = inv;               // expf(0)*inv
            g_pval[N + tok] = expf(b1 - b0) * inv;
        }
    }
}

// ---------------------------------------------------------------------------
// Rank: ordered per-expert cumsum (k-major, token order) via match_any+popc
// within warp, per-expert cross-warp scan by warps 0..7. Pure compute.
// ---------------------------------------------------------------------------
__global__ void __launch_bounds__(1024) rank_kernel(int N)
{
    const int tid  = threadIdx.x;
    const int warp = tid >> 5;
    const int lane = tid & 31;
    const int total = 2 * N;

    __shared__ int warpcnt[N_EXP][32];
    __shared__ int basesh[N_EXP][32];
    __shared__ int running[N_EXP];
    if (tid < N_EXP) running[tid] = 0;

    const int rounds = (total + 1023) >> 10;
    for (int rd = 0; rd < rounds; rd++) {
        const int i = rd * 1024 + tid;
        const int e = (i < total) ? g_eidx[i] : -1;

        if (tid < N_EXP * 32) ((int*)warpcnt)[tid] = 0;
        __syncthreads();

        unsigned m = __match_any_sync(0xFFFFFFFFu, e);
        int lrank  = __popc(m & ((1u << lane) - 1u));
        int leader = __ffs(m) - 1;
        if (e >= 0 && lane == leader)
            warpcnt[e][warp] = __popc(m);
        __syncthreads();

        if (warp < N_EXP) {
            int runv = running[warp];
            int v = warpcnt[warp][lane];
            int s = v;
#pragma unroll
            for (int off = 1; off < 32; off <<= 1) {
                int u = __shfl_up_sync(0xFFFFFFFFu, s, off);
                if (lane >= off) s += u;
            }
            basesh[warp][lane] = runv + s - v;   // exclusive + running
            if (lane == 31) running[warp] = runv + s;
        }
        __syncthreads();

        if (e >= 0)
            g_rank[i] = basesh[e][warp] + lrank;
        __syncthreads();
    }

    if (tid < N_EXP)
        g_total[tid] = running[tid];
}

// ---------------------------------------------------------------------------
// Scatter: one thread per routed entry, at most 2 stores into the zeroed
// output. Block 0 writes used_capacity.
// ---------------------------------------------------------------------------
__global__ void __launch_bounds__(256) scatter_kernel(
    float* __restrict__ out, int N, int C)
{
    const int i = blockIdx.x * blockDim.x + threadIdx.x;
    const int total = 2 * N;
    const long long rowsC = (long long)N * N_EXP * (long long)C;

    if (i < total) {
        int r = g_rank[i];
        if (r < C) {
            int e = g_eidx[i];
            int k = (i >= N) ? 1 : 0;
            int n = i - k * N;
            long long pos = ((long long)n * N_EXP + e) * (long long)C + r;
            out[8 + pos]         = g_pval[i];
            out[8 + rowsC + pos] = 1.0f;
        }
    }

    if (blockIdx.x == 0 && threadIdx.x < N_EXP) {
        int uc = g_total[threadIdx.x];
        if (uc > C) uc = C;
        out[threadIdx.x] = (float)uc;
    }
}

// ---------------------------------------------------------------------------
extern "C" void kernel_launch(void* const* d_in, const int* in_sizes, int n_in,
                              void* d_out, int out_size)
{
    const float* x   = (const float*)d_in[0];
    const float* w_g = (const float*)d_in[1];
    float* out = (float*)d_out;

    const int D = in_sizes[1] / N_EXP;   // 1024
    const int N = in_sizes[0] / D;       // 4096 tokens

    int C = (int)floorf(2.0f * 1.25f * (float)N / (float)N_EXP);
    C += (C & 1);
    if (C < 4) C = 4;

    // 1) zero the full output (HBM-write floor for 336MB)
    cudaMemsetAsync(d_out, 0, (size_t)out_size * sizeof(float));

    // 2) router: split-D, 2 warps/token, x prefetched (MLP=4), 1024 blocks
    int blocks = (N + 3) / 4;
    router_topk_kernel<<<blocks, 256>>>(x, w_g, N);

    // 3) ordered ranks (pure compute, single 1024-thread block)
    rank_kernel<<<1, 1024>>>(N);

    // 4) wide-grid scatter + used_capacity
    int sblocks = (2 * N + 255) / 256;
    scatter_kernel<<<sblocks, 256>>>(out, N, C);
}